// round 14
// baseline (speedup 1.0000x reference)
#include <cuda_runtime.h>
#include <cuda_bf16.h>

// Fixed shapes per reference: B=4096 users, P=200 slots, tau=1.0
#define NB 4096
#define PMAX 200
#define PROWS 224          // row slots (pos/2), padded with -1e30
#define NTHREADS 256
#define NBLOCKS 1184       // 148 SMs x 8 resident blocks: exactly one wave
#define ROWPAD -1.0e30f    // tanh(-huge) = -1 exactly -> pair term 0 after +0.5
#define COLPAD  1.0e30f

// Scratch (no device allocation allowed -> __device__ globals)
__device__ float g_block_loss[NB];
__device__ unsigned int g_next = 0;        // work-stealing ticket
__device__ unsigned int g_done_count = 0;

__device__ __forceinline__ float fast_tanh(float x) {
    float r;
    asm("tanh.approx.f32 %0, %1;" : "=f"(r) : "f"(x));
    return r;
}

// sigmoid(p - n) = 0.5*tanh((p-n)/2) + 0.5.  With ph=p/2, nh=n/2:
//   term = 0.5*tanh(ph - nh) + 0.5
// +0.5 baselines added analytically (nIters*NC per thread, exact in fp32);
// padded rows/cols give tanh = -1.0 exactly -> contribution 0.
// Per pair: FADD + MUFU.TANH + FFMA(0.5 imm).
template<int NC>
__device__ __forceinline__ float pair_sum(const float2* __restrict__ ph2,
                                          const float* __restrict__ neg_g,
                                          int p, int nIters, int tx, int wy)
{
    float nh[NC];
    #pragma unroll
    for (int c = 0; c < NC; c++) {
        int j = c * 32 + tx;
        nh[c] = (j < p) ? (0.5f * neg_g[j]) : COLPAD;
    }
    float acc0 = 0.0f, acc1 = 0.0f;
    for (int r = 0; r < nIters; r++) {
        float2 e01 = ph2[r * 8 + wy];        // rows 2k, 2k+1 (k = 8r+wy)
        const float e0 = e01.x, e1 = e01.y;
        #pragma unroll
        for (int c = 0; c < NC; c++) {
            float t0 = fast_tanh(e0 - nh[c]);
            float t1 = fast_tanh(e1 - nh[c]);
            acc0 = fmaf(0.5f, t0, acc0);
            acc1 = fmaf(0.5f, t1, acc1);
        }
    }
    return acc0 + acc1 + (float)(nIters * NC);
}

__global__ __launch_bounds__(NTHREADS) void sauc_kernel(
    const float* __restrict__ scores_pos,
    const float* __restrict__ scores_neg,
    const int* __restrict__ pos_counts,
    float* __restrict__ out)
{
    const int tid = threadIdx.x;
    const int tx = tid & 31;
    const int wy = tid >> 5;

    __shared__ __align__(8) float s_ph[PROWS];
    __shared__ float s_warp[NTHREADS / 32];
    __shared__ unsigned int s_u;
    __shared__ unsigned int s_is_last;

    // Persistent loop: dynamically claim users until exhausted.
    for (;;) {
        if (tid == 0) s_u = atomicAdd(&g_next, 1u);
        __syncthreads();                       // A: claim visible; prior reads done
        const unsigned int b = s_u;
        if (b >= NB) break;                    // block-uniform exit

        const int p = pos_counts[b];
        if (tid < PROWS)
            s_ph[tid] = (tid < (unsigned)p) ? (0.5f * scores_pos[b * PMAX + tid])
                                            : ROWPAD;
        __syncthreads();                       // B: s_ph ready

        const float2* ph2 = (const float2*)s_ph;
        const float* neg_g = scores_neg + b * PMAX;
        const int nc = (p + 31) >> 5;          // 1..7, block-uniform
        const int kpairs = (p + 1) >> 1;
        const int dk = kpairs - wy;
        const int nIters = (dk > 0) ? ((dk + 7) >> 3) : 0;   // warp-uniform

        float acc;
        switch (nc) {
            case 1:  acc = pair_sum<1>(ph2, neg_g, p, nIters, tx, wy); break;
            case 2:  acc = pair_sum<2>(ph2, neg_g, p, nIters, tx, wy); break;
            case 3:  acc = pair_sum<3>(ph2, neg_g, p, nIters, tx, wy); break;
            case 4:  acc = pair_sum<4>(ph2, neg_g, p, nIters, tx, wy); break;
            case 5:  acc = pair_sum<5>(ph2, neg_g, p, nIters, tx, wy); break;
            case 6:  acc = pair_sum<6>(ph2, neg_g, p, nIters, tx, wy); break;
            default: acc = pair_sum<7>(ph2, neg_g, p, nIters, tx, wy); break;
        }

        #pragma unroll
        for (int off = 16; off > 0; off >>= 1)
            acc += __shfl_down_sync(0xffffffffu, acc, off);
        if ((tid & 31) == 0) s_warp[tid >> 5] = acc;
        __syncthreads();                       // C: all compute on s_ph done
        if (tid == 0) {
            float v = 0.0f;
            #pragma unroll
            for (int w = 0; w < NTHREADS / 32; w++) v += s_warp[w];
            float pf = (float)p;
            g_block_loss[b] = 1.0f - v / (pf * pf);
        }
    }

    // All blocks arrive here after the ticket is exhausted.
    if (tid == 0) {
        __threadfence();
        s_is_last = (atomicAdd(&g_done_count, 1u) == (unsigned)(NBLOCKS - 1));
    }
    __syncthreads();

    // Last block performs the deterministic fixed-tree mean over 4096 losses.
    if (s_is_last) {
        __threadfence();
        __shared__ float s_red[NTHREADS];
        float a = 0.0f;
        #pragma unroll
        for (int i = tid; i < NB; i += NTHREADS)
            a += g_block_loss[i];
        s_red[tid] = a;
        __syncthreads();
        #pragma unroll
        for (int stride = NTHREADS / 2; stride >= 32; stride >>= 1) {
            if (tid < stride) s_red[tid] += s_red[tid + stride];
            __syncthreads();
        }
        if (tid < 32) {
            float v = s_red[tid];
            #pragma unroll
            for (int off = 16; off > 0; off >>= 1)
                v += __shfl_down_sync(0xffffffffu, v, off);
            if (tid == 0) {
                out[0] = v * (1.0f / (float)NB);
                g_next = 0;         // reset tickets for next graph replay
                g_done_count = 0;
            }
        }
    }
}

extern "C" void kernel_launch(void* const* d_in, const int* in_sizes, int n_in,
                              void* d_out, int out_size)
{
    const float* scores_pos = (const float*)d_in[0];
    const float* scores_neg = (const float*)d_in[1];
    const int*   pos_counts = (const int*)d_in[2];
    float* out = (float*)d_out;

    sauc_kernel<<<NBLOCKS, NTHREADS>>>(scores_pos, scores_neg, pos_counts, out);
}